// round 5
// baseline (speedup 1.0000x reference)
#include <cuda_runtime.h>
#include <math.h>

#define NMAX 100000
#define EMAX 1600000
#define HDIM 128
#define C_OUT 20

// ---- static device scratch (no allocation allowed) ----
__device__ float4 g_agg[(size_t)NMAX * HDIM / 4];   // aggregation / temp buffer
__device__ float4 g_h[(size_t)NMAX * HDIM / 4];     // layer activations
__device__ int    g_hist[NMAX];
__device__ int    g_rowptr[NMAX + 1];
__device__ int    g_wofs[NMAX];
__device__ int    g_srcs[EMAX];
__device__ int    g_bsum[128];
__device__ int    g_is64;                            // 1 if edge_index is int64 on device

// ---------------- dtype detection for edge_index ----------------
// Sample ONLY int64-elements [0, e): word index <= 2e-1, which is in-bounds
// whether the buffer holds 2e int32 words or 4e words (2e int64).
// int64 data (values < 2^31): all sampled high words are 0  -> is64 stays 1.
// int32 data: sampled "high words" are row-0 src indices    -> some nonzero -> is64=0.
__global__ void k_detect(const unsigned* __restrict__ ei_raw, int e) {
    int t = threadIdx.x;
    if (t == 0) g_is64 = 1;
    __syncthreads();
    long long stride = (long long)e / 256;
    if (stride < 1) stride = 1;
    long long idx = (long long)t * stride;
    if (idx < (long long)e) {
        unsigned hi = ei_raw[2 * idx + 1];
        if (hi != 0) atomicAnd(&g_is64, 0);
    }
}

__device__ __forceinline__ int load_edge(const void* ei, long long ofs) {
    if (g_is64) return (int)((const long long*)ei)[ofs];
    return ((const int*)ei)[ofs];
}

// ---------------- CSR build ----------------

__global__ void k_zero_hist(int n) {
    int i = blockIdx.x * blockDim.x + threadIdx.x;
    if (i < n) g_hist[i] = 0;
}

__global__ void k_hist(const void* __restrict__ ei, int e, int n) {
    int i = blockIdx.x * blockDim.x + threadIdx.x;
    if (i < e) {
        int d = load_edge(ei, (long long)e + i);
        if ((unsigned)d < (unsigned)n) atomicAdd(&g_hist[d], 1);
    }
}

// scan phase 1: per-block (2048 elems) sums
__global__ void k_scan1(int n) {
    __shared__ int sh[512];
    int b = blockIdx.x, t = threadIdx.x;
    int base = b * 2048 + t * 4;
    int s = 0;
#pragma unroll
    for (int i = 0; i < 4; i++) {
        int idx = base + i;
        if (idx < n) s += g_hist[idx];
    }
    sh[t] = s;
    __syncthreads();
    for (int off = 256; off > 0; off >>= 1) {
        if (t < off) sh[t] += sh[t + off];
        __syncthreads();
    }
    if (t == 0) g_bsum[b] = sh[0];
}

// scan phase 2: exclusive scan of block sums (single block)
__global__ void k_scan2(int nb, int n) {
    __shared__ int sh[128];
    int t = threadIdx.x;
    int v = (t < nb) ? g_bsum[t] : 0;
    sh[t] = v;
    __syncthreads();
    for (int off = 1; off < 128; off <<= 1) {
        int a = (t >= off) ? sh[t - off] : 0;
        __syncthreads();
        sh[t] += a;
        __syncthreads();
    }
    int ex = (t == 0) ? 0 : sh[t - 1];
    if (t < nb) g_bsum[t] = ex;
    if (t == 127) g_rowptr[n] = sh[127];
}

// scan phase 3: write rowptr / write offsets
__global__ void k_scan3(int n) {
    __shared__ int sh[512];
    int b = blockIdx.x, t = threadIdx.x;
    int base = b * 2048 + t * 4;
    int v[4];
    int s = 0;
#pragma unroll
    for (int i = 0; i < 4; i++) {
        int idx = base + i;
        v[i] = (idx < n) ? g_hist[idx] : 0;
        s += v[i];
    }
    sh[t] = s;
    __syncthreads();
    for (int off = 1; off < 512; off <<= 1) {
        int a = (t >= off) ? sh[t - off] : 0;
        __syncthreads();
        sh[t] += a;
        __syncthreads();
    }
    int run = g_bsum[b] + ((t == 0) ? 0 : sh[t - 1]);
#pragma unroll
    for (int i = 0; i < 4; i++) {
        int idx = base + i;
        if (idx < n) {
            g_rowptr[idx] = run;
            g_wofs[idx] = run;
            run += v[i];
        }
    }
}

__global__ void k_scatter(const void* __restrict__ ei, int e, int n) {
    int i = blockIdx.x * blockDim.x + threadIdx.x;
    if (i < e) {
        int d = load_edge(ei, (long long)e + i);
        int s = load_edge(ei, i);
        if ((unsigned)d < (unsigned)n && (unsigned)s < (unsigned)n) {
            int pos = atomicAdd(&g_wofs[d], 1);
            if ((unsigned)pos < (unsigned)EMAX) g_srcs[pos] = s;
        }
    }
}

// ---------------- mean aggregation: warp per node ----------------
// SRC_X: input X comes from the x pointer param; else from g_h. Output: g_agg.

template <bool SRC_X>
__global__ void k_aggregate(const float4* __restrict__ xin, int n) {
    const float4* X = SRC_X ? xin : (const float4*)g_h;
    int w = (blockIdx.x * blockDim.x + threadIdx.x) >> 5;
    int lane = threadIdx.x & 31;
    if (w >= n) return;
    int beg = g_rowptr[w], end = g_rowptr[w + 1];
    float4 acc = make_float4(0.f, 0.f, 0.f, 0.f);
    int e = beg;
    for (; e + 1 < end; e += 2) {
        int s0 = g_srcs[e], s1 = g_srcs[e + 1];
        float4 v0 = X[(size_t)s0 * 32 + lane];
        float4 v1 = X[(size_t)s1 * 32 + lane];
        acc.x += v0.x + v1.x; acc.y += v0.y + v1.y;
        acc.z += v0.z + v1.z; acc.w += v0.w + v1.w;
    }
    if (e < end) {
        int s0 = g_srcs[e];
        float4 v0 = X[(size_t)s0 * 32 + lane];
        acc.x += v0.x; acc.y += v0.y; acc.z += v0.z; acc.w += v0.w;
    }
    int cnt = end - beg;
    float inv = 1.0f / (float)(cnt > 0 ? cnt : 1);
    float4 r = make_float4(acc.x * inv, acc.y * inv, acc.z * inv, acc.w * inv);
    g_agg[(size_t)w * 32 + lane] = r;
}

// ---------------- fused GEMM: C = relu(Am @ Wl^T [+ Ax @ Wr^T] + bias) ----------------
// 64 nodes x 128 outs per block, 256 threads, 4x8 register tile per thread,
// K chunked by 16, stride-17 smem (conflict-free). Static smem = 25.5 KB.
//
// MODE 0: Am=g_agg, Ax=xin (param), out=g_h   (layer 1, dual)
// MODE 1: Am=g_agg, Ax=g_h,         out=g_h   (layer 2, dual)
// MODE 2: Am=g_h,   no Ax,          out=g_agg (MLP layer, single)

template <int MODE>
__global__ __launch_bounds__(256) void k_gemm(
    const float* __restrict__ xin,
    const float* __restrict__ Wl, const float* __restrict__ Wr,
    const float* __restrict__ bias, int n)
{
    constexpr bool DUAL = (MODE != 2);
    __shared__ float sAm[64 * 17];
    __shared__ float sAx[DUAL ? 64 * 17 : 1];
    __shared__ float sWl[128 * 17];
    __shared__ float sWr[DUAL ? 128 * 17 : 1];

    const float* Am = (MODE == 2) ? (const float*)g_h : (const float*)g_agg;
    const float* Ax = (MODE == 0) ? xin : (const float*)g_h;
    float* Cout = (MODE == 2) ? (float*)g_agg : (float*)g_h;

    int t = threadIdx.x;
    int tm = t >> 4;      // 0..15 -> node group (4 nodes)
    int tn = t & 15;      // 0..15 -> out group (8 outs, stride 16)
    int i0 = blockIdx.x * 64;

    float acc[4][8];
#pragma unroll
    for (int i = 0; i < 4; i++)
#pragma unroll
        for (int j = 0; j < 8; j++) acc[i][j] = 0.f;

    for (int kc = 0; kc < 128; kc += 16) {
        // load A tiles (64x16 each): 1024 elems, 4 per thread
#pragma unroll
        for (int r = 0; r < 4; r++) {
            int lin = t + r * 256;
            int m = lin >> 4, k = lin & 15;
            int row = i0 + m;
            float vm = 0.f, vx = 0.f;
            if (row < n) {
                vm = Am[(size_t)row * 128 + kc + k];
                if (DUAL) vx = Ax[(size_t)row * 128 + kc + k];
            }
            sAm[m * 17 + k] = vm;
            if (DUAL) sAx[m * 17 + k] = vx;
        }
        // load W tiles (128x16 each): 2048 elems, 8 per thread
#pragma unroll
        for (int r = 0; r < 8; r++) {
            int lin = t + r * 256;
            int o = lin >> 4, k = lin & 15;
            sWl[o * 17 + k] = Wl[o * 128 + kc + k];
            if (DUAL) sWr[o * 17 + k] = Wr[o * 128 + kc + k];
        }
        __syncthreads();

#pragma unroll
        for (int k = 0; k < 16; k++) {
            float am[4], axv[4], wl[8], wr[8];
#pragma unroll
            for (int i = 0; i < 4; i++) {
                am[i] = sAm[(tm * 4 + i) * 17 + k];
                if (DUAL) axv[i] = sAx[(tm * 4 + i) * 17 + k];
            }
#pragma unroll
            for (int j = 0; j < 8; j++) {
                wl[j] = sWl[(tn + 16 * j) * 17 + k];
                if (DUAL) wr[j] = sWr[(tn + 16 * j) * 17 + k];
            }
#pragma unroll
            for (int i = 0; i < 4; i++)
#pragma unroll
                for (int j = 0; j < 8; j++) {
                    acc[i][j] = fmaf(am[i], wl[j], acc[i][j]);
                    if (DUAL) acc[i][j] = fmaf(axv[i], wr[j], acc[i][j]);
                }
        }
        __syncthreads();
    }

#pragma unroll
    for (int i = 0; i < 4; i++) {
        int row = i0 + tm * 4 + i;
        if (row >= n) continue;
#pragma unroll
        for (int j = 0; j < 8; j++) {
            int o = tn + 16 * j;
            float v = acc[i][j] + bias[o];
            v = fmaxf(v, 0.f);
            Cout[(size_t)row * 128 + o] = v;
        }
    }
}

// ---------------- head: out = sigmoid(g_agg @ Wm2^T + bm2), warp per node x4 ----------------

__global__ void k_head(const float* __restrict__ Wm2,
                       const float* __restrict__ bm2, float* __restrict__ out, int n)
{
    __shared__ __align__(16) float sW[C_OUT * HDIM];
    __shared__ float sb[C_OUT];
    int t = threadIdx.x;
    for (int i = t; i < C_OUT * HDIM; i += blockDim.x) sW[i] = Wm2[i];
    if (t < C_OUT) sb[t] = bm2[t];
    __syncthreads();

    const float4* T1 = (const float4*)g_agg;
    int warp_id = (blockIdx.x * blockDim.x + t) >> 5;  // global warp
    int lane = t & 31;

    for (int v = 0; v < 4; v++) {
        int node = warp_id * 4 + v;
        if (node >= n) return;
        float4 h = T1[(size_t)node * 32 + lane];
#pragma unroll
        for (int o = 0; o < C_OUT; o++) {
            float4 wv = *((const float4*)(sW + o * HDIM) + lane);
            float p = h.x * wv.x + h.y * wv.y + h.z * wv.z + h.w * wv.w;
            p += __shfl_xor_sync(0xFFFFFFFFu, p, 16);
            p += __shfl_xor_sync(0xFFFFFFFFu, p, 8);
            p += __shfl_xor_sync(0xFFFFFFFFu, p, 4);
            p += __shfl_xor_sync(0xFFFFFFFFu, p, 2);
            p += __shfl_xor_sync(0xFFFFFFFFu, p, 1);
            if (lane == o) {
                float z = p + sb[o];
                out[(size_t)node * C_OUT + o] = 1.f / (1.f + __expf(-z));
            }
        }
    }
}

// ---------------- launch ----------------

extern "C" void kernel_launch(void* const* d_in, const int* in_sizes, int n_in,
                              void* d_out, int out_size)
{
    const float* x   = (const float*)d_in[0];
    const void*  ei  = d_in[1];
    const float* W1l = (const float*)d_in[2];
    const float* b1  = (const float*)d_in[3];
    const float* W1r = (const float*)d_in[4];
    const float* W2l = (const float*)d_in[5];
    const float* b2  = (const float*)d_in[6];
    const float* W2r = (const float*)d_in[7];
    const float* Wm1 = (const float*)d_in[8];
    const float* bm1 = (const float*)d_in[9];
    const float* Wm2 = (const float*)d_in[10];
    const float* bm2 = (const float*)d_in[11];
    float* out = (float*)d_out;

    int n = in_sizes[0] / HDIM;
    int e = in_sizes[1] / 2;

    // dtype detection + CSR build (deterministic given inputs up to fp-add order)
    k_detect<<<1, 256>>>((const unsigned*)ei, e);
    k_zero_hist<<<(n + 255) / 256, 256>>>(n);
    k_hist<<<(e + 255) / 256, 256>>>(ei, e, n);
    int nb = (n + 2047) / 2048;
    k_scan1<<<nb, 512>>>(n);
    k_scan2<<<1, 128>>>(nb, n);
    k_scan3<<<nb, 512>>>(n);
    k_scatter<<<(e + 255) / 256, 256>>>(ei, e, n);

    int aggBlocks = (n + 7) / 8;            // warp per node, 8 warps/block
    int gemmBlocks = (n + 63) / 64;

    // layer 1
    k_aggregate<true><<<aggBlocks, 256>>>((const float4*)x, n);
    k_gemm<0><<<gemmBlocks, 256>>>(x, W1l, W1r, b1, n);
    // layer 2
    k_aggregate<false><<<aggBlocks, 256>>>(nullptr, n);
    k_gemm<1><<<gemmBlocks, 256>>>(nullptr, W2l, W2r, b2, n);
    // MLP layer 1
    k_gemm<2><<<gemmBlocks, 256>>>(nullptr, Wm1, nullptr, bm1, n);
    // head
    int headBlocks = (n + 31) / 32;         // 8 warps/block * 4 nodes/warp
    k_head<<<headBlocks, 256>>>(Wm2, bm2, out, n);
}

// round 7
// speedup vs baseline: 1.6080x; 1.6080x over previous
#include <cuda_runtime.h>
#include <math.h>
#include <stdint.h>

#define NMAX 100000
#define EMAX 1600000
#define HDIM 128
#define C_OUT 20

// ---- static device scratch (no allocation allowed) ----
__device__ float4 g_agg[(size_t)NMAX * HDIM / 4];   // aggregation / temp buffer
__device__ float4 g_h[(size_t)NMAX * HDIM / 4];     // layer activations
__device__ int    g_hist[NMAX];
__device__ int    g_rowptr[NMAX + 1];
__device__ int    g_wofs[NMAX];
__device__ int    g_srcs[EMAX];
__device__ int    g_bsum[128];
__device__ int    g_is64;

// ================= helpers =================

__device__ __forceinline__ uint32_t cvt_tf32(float f) {
    uint32_t u;
    asm("cvt.rna.tf32.f32 %0, %1;" : "=r"(u) : "f"(f));
    return u;
}

// D = A(16x8, tf32 row) * B(8x8, tf32 col) + C, fp32 accum
__device__ __forceinline__ void mma_tf32(float* c, const uint32_t* a, const uint32_t* b) {
    asm volatile(
        "mma.sync.aligned.m16n8k8.row.col.f32.tf32.tf32.f32 "
        "{%0,%1,%2,%3}, {%4,%5,%6,%7}, {%8,%9}, {%0,%1,%2,%3};"
        : "+f"(c[0]), "+f"(c[1]), "+f"(c[2]), "+f"(c[3])
        : "r"(a[0]), "r"(a[1]), "r"(a[2]), "r"(a[3]),
          "r"(b[0]), "r"(b[1]));
}

// ================= dtype detection for edge_index =================
__global__ void k_detect(const unsigned* __restrict__ ei_raw, int e) {
    int t = threadIdx.x;
    if (t == 0) g_is64 = 1;
    __syncthreads();
    long long stride = (long long)e / 256;
    if (stride < 1) stride = 1;
    long long idx = (long long)t * stride;
    if (idx < (long long)e) {
        unsigned hi = ei_raw[2 * idx + 1];
        if (hi != 0) atomicAnd(&g_is64, 0);
    }
}

__device__ __forceinline__ int load_edge(const void* ei, long long ofs) {
    if (g_is64) return (int)((const long long*)ei)[ofs];
    return ((const int*)ei)[ofs];
}

// ================= CSR build =================

__global__ void k_zero_hist(int n) {
    int i = blockIdx.x * blockDim.x + threadIdx.x;
    if (i < n) g_hist[i] = 0;
}

__global__ void k_hist(const void* __restrict__ ei, int e, int n) {
    int i = blockIdx.x * blockDim.x + threadIdx.x;
    if (i < e) {
        int d = load_edge(ei, (long long)e + i);
        if ((unsigned)d < (unsigned)n) atomicAdd(&g_hist[d], 1);
    }
}

__global__ void k_scan1(int n) {
    __shared__ int sh[512];
    int b = blockIdx.x, t = threadIdx.x;
    int base = b * 2048 + t * 4;
    int s = 0;
#pragma unroll
    for (int i = 0; i < 4; i++) {
        int idx = base + i;
        if (idx < n) s += g_hist[idx];
    }
    sh[t] = s;
    __syncthreads();
    for (int off = 256; off > 0; off >>= 1) {
        if (t < off) sh[t] += sh[t + off];
        __syncthreads();
    }
    if (t == 0) g_bsum[b] = sh[0];
}

__global__ void k_scan2(int nb, int n) {
    __shared__ int sh[128];
    int t = threadIdx.x;
    int v = (t < nb) ? g_bsum[t] : 0;
    sh[t] = v;
    __syncthreads();
    for (int off = 1; off < 128; off <<= 1) {
        int a = (t >= off) ? sh[t - off] : 0;
        __syncthreads();
        sh[t] += a;
        __syncthreads();
    }
    int ex = (t == 0) ? 0 : sh[t - 1];
    if (t < nb) g_bsum[t] = ex;
    if (t == 127) g_rowptr[n] = sh[127];
}

__global__ void k_scan3(int n) {
    __shared__ int sh[512];
    int b = blockIdx.x, t = threadIdx.x;
    int base = b * 2048 + t * 4;
    int v[4];
    int s = 0;
#pragma unroll
    for (int i = 0; i < 4; i++) {
        int idx = base + i;
        v[i] = (idx < n) ? g_hist[idx] : 0;
        s += v[i];
    }
    sh[t] = s;
    __syncthreads();
    for (int off = 1; off < 512; off <<= 1) {
        int a = (t >= off) ? sh[t - off] : 0;
        __syncthreads();
        sh[t] += a;
        __syncthreads();
    }
    int run = g_bsum[b] + ((t == 0) ? 0 : sh[t - 1]);
#pragma unroll
    for (int i = 0; i < 4; i++) {
        int idx = base + i;
        if (idx < n) {
            g_rowptr[idx] = run;
            g_wofs[idx] = run;
            run += v[i];
        }
    }
}

__global__ void k_scatter(const void* __restrict__ ei, int e, int n) {
    int i = blockIdx.x * blockDim.x + threadIdx.x;
    if (i < e) {
        int d = load_edge(ei, (long long)e + i);
        int s = load_edge(ei, i);
        if ((unsigned)d < (unsigned)n && (unsigned)s < (unsigned)n) {
            int pos = atomicAdd(&g_wofs[d], 1);
            if ((unsigned)pos < (unsigned)EMAX) g_srcs[pos] = s;
        }
    }
}

// ================= mean aggregation: warp per node =================

template <bool SRC_X>
__global__ void k_aggregate(const float4* __restrict__ xin, int n) {
    const float4* X = SRC_X ? xin : (const float4*)g_h;
    int w = (blockIdx.x * blockDim.x + threadIdx.x) >> 5;
    int lane = threadIdx.x & 31;
    if (w >= n) return;
    int beg = g_rowptr[w], end = g_rowptr[w + 1];
    float4 acc = make_float4(0.f, 0.f, 0.f, 0.f);
    int e = beg;
    for (; e + 1 < end; e += 2) {
        int s0 = g_srcs[e], s1 = g_srcs[e + 1];
        float4 v0 = X[(size_t)s0 * 32 + lane];
        float4 v1 = X[(size_t)s1 * 32 + lane];
        acc.x += v0.x + v1.x; acc.y += v0.y + v1.y;
        acc.z += v0.z + v1.z; acc.w += v0.w + v1.w;
    }
    if (e < end) {
        int s0 = g_srcs[e];
        float4 v0 = X[(size_t)s0 * 32 + lane];
        acc.x += v0.x; acc.y += v0.y; acc.z += v0.z; acc.w += v0.w;
    }
    int cnt = end - beg;
    float inv = 1.0f / (float)(cnt > 0 ? cnt : 1);
    float4 r = make_float4(acc.x * inv, acc.y * inv, acc.z * inv, acc.w * inv);
    g_agg[(size_t)w * 32 + lane] = r;
}

// ================= tf32 mma.sync GEMM =================
// C[tile 128 x 128] = relu( Am @ Wl^T [+ Ax @ Wr^T] + bias )
// 256 threads = 8 warps (4M x 2N), warp tile 32x64, m16n8k8 fragments.
// MODE 0: Am=g_agg, Ax=xparam, out=g_h   (layer 1, dual)
// MODE 1: Am=g_agg, Ax=g_h,    out=g_h   (layer 2, dual)
// MODE 2: Am=g_h,   single,    out=g_agg (MLP layer)

#define SROW 132   // padded row length (floats), conflict-free fragment LDS

template <int MODE>
__global__ __launch_bounds__(256, 1) void k_mmagemm(
    const float4* __restrict__ xparam,
    const float4* __restrict__ Wl, const float4* __restrict__ Wr,
    const float* __restrict__ bias, int n)
{
    constexpr bool DUAL = (MODE != 2);
    extern __shared__ uint32_t smem[];           // sA[128*SROW] then sW[128*SROW]
    uint32_t* sA = smem;
    uint32_t* sW = smem + 128 * SROW;
    __shared__ float sbias[128];

    const float4* Am4 = (MODE == 2) ? (const float4*)g_h : (const float4*)g_agg;
    const float4* Ax4 = (MODE == 0) ? xparam : (const float4*)g_h;
    float* Cout = (MODE == 2) ? (float*)g_agg : (float*)g_h;

    int tid = threadIdx.x;
    int lane = tid & 31, wid = tid >> 5;
    int wm = wid >> 1, wn = wid & 1;             // warp grid 4 x 2
    int g = lane >> 2, t = lane & 3;
    int row0 = blockIdx.x * 128;

    if (tid < 128) sbias[tid] = bias[tid];

    float c[2][8][4];
#pragma unroll
    for (int mi = 0; mi < 2; mi++)
#pragma unroll
        for (int ni = 0; ni < 8; ni++)
#pragma unroll
            for (int q = 0; q < 4; q++) c[mi][ni][q] = 0.f;

    const int NPASS = DUAL ? 2 : 1;
    for (int pass = 0; pass < NPASS; pass++) {
        const float4* Asrc = (pass == 0) ? Am4 : Ax4;
        const float4* Wsrc = (pass == 0) ? Wl : Wr;
        __syncthreads();   // previous pass consumers done before overwrite
        // ---- stage A (128 x 128) and W (128 x 128) as tf32, coalesced ----
        for (int i = tid; i < 4096; i += 256) {
            int r = i >> 5, kq = i & 31;         // one warp = one row (32 float4)
            int grow = row0 + r;
            float4 v = make_float4(0.f, 0.f, 0.f, 0.f);
            if (grow < n) v = Asrc[(size_t)grow * 32 + kq];
            uint32_t* pa = sA + r * SROW + kq * 4;
            pa[0] = cvt_tf32(v.x); pa[1] = cvt_tf32(v.y);
            pa[2] = cvt_tf32(v.z); pa[3] = cvt_tf32(v.w);
            float4 w = Wsrc[i];
            uint32_t* pw = sW + r * SROW + kq * 4;
            pw[0] = cvt_tf32(w.x); pw[1] = cvt_tf32(w.y);
            pw[2] = cvt_tf32(w.z); pw[3] = cvt_tf32(w.w);
        }
        __syncthreads();

        // ---- K loop: 16 steps of k8 ----
#pragma unroll
        for (int k0 = 0; k0 < 128; k0 += 8) {
            uint32_t a[2][4];
#pragma unroll
            for (int mi = 0; mi < 2; mi++) {
                int rb = wm * 32 + mi * 16;
                const uint32_t* p0 = sA + (rb + g) * SROW + k0 + t;
                const uint32_t* p1 = sA + (rb + 8 + g) * SROW + k0 + t;
                a[mi][0] = p0[0]; a[mi][1] = p1[0];
                a[mi][2] = p0[4]; a[mi][3] = p1[4];
            }
            uint32_t b[8][2];
#pragma unroll
            for (int ni = 0; ni < 8; ni++) {
                const uint32_t* p = sW + (wn * 64 + ni * 8 + g) * SROW + k0 + t;
                b[ni][0] = p[0]; b[ni][1] = p[4];
            }
#pragma unroll
            for (int mi = 0; mi < 2; mi++)
#pragma unroll
                for (int ni = 0; ni < 8; ni++)
                    mma_tf32(c[mi][ni], a[mi], b[ni]);
        }
    }
    __syncthreads();

    // ---- epilogue: bias + relu, float2 stores ----
#pragma unroll
    for (int mi = 0; mi < 2; mi++) {
#pragma unroll
        for (int h = 0; h < 2; h++) {
            int row = row0 + wm * 32 + mi * 16 + h * 8 + g;
            if (row >= n) continue;
            float* dst = Cout + (size_t)row * 128;
#pragma unroll
            for (int ni = 0; ni < 8; ni++) {
                int col = wn * 64 + ni * 8 + 2 * t;
                float2 o;
                o.x = fmaxf(c[mi][ni][h * 2 + 0] + sbias[col], 0.f);
                o.y = fmaxf(c[mi][ni][h * 2 + 1] + sbias[col + 1], 0.f);
                *(float2*)(dst + col) = o;
            }
        }
    }
}

// ================= head: out = sigmoid(g_agg @ Wm2^T + bm2) =================

__global__ void k_head(const float* __restrict__ Wm2,
                       const float* __restrict__ bm2, float* __restrict__ out, int n)
{
    __shared__ __align__(16) float sW[C_OUT * HDIM];
    __shared__ float sb[C_OUT];
    int t = threadIdx.x;
    for (int i = t; i < C_OUT * HDIM; i += blockDim.x) sW[i] = Wm2[i];
    if (t < C_OUT) sb[t] = bm2[t];
    __syncthreads();

    const float4* T1 = (const float4*)g_agg;
    int warp_id = (blockIdx.x * blockDim.x + t) >> 5;
    int lane = t & 31;

    for (int v = 0; v < 4; v++) {
        int node = warp_id * 4 + v;
        if (node >= n) return;
        float4 h = T1[(size_t)node * 32 + lane];
#pragma unroll
        for (int o = 0; o < C_OUT; o++) {
            float4 wv = *((const float4*)(sW + o * HDIM) + lane);
            float p = h.x * wv.x + h.y * wv.y + h.z * wv.z + h.w * wv.w;
            p += __shfl_xor_sync(0xFFFFFFFFu, p, 16);
            p += __shfl_xor_sync(0xFFFFFFFFu, p, 8);
            p += __shfl_xor_sync(0xFFFFFFFFu, p, 4);
            p += __shfl_xor_sync(0xFFFFFFFFu, p, 2);
            p += __shfl_xor_sync(0xFFFFFFFFu, p, 1);
            if (lane == o) {
                float z = p + sb[o];
                out[(size_t)node * C_OUT + o] = 1.f / (1.f + __expf(-z));
            }
        }
    }
}

// ================= launch =================

extern "C" void kernel_launch(void* const* d_in, const int* in_sizes, int n_in,
                              void* d_out, int out_size)
{
    const float* x   = (const float*)d_in[0];
    const void*  ei  = d_in[1];
    const float* W1l = (const float*)d_in[2];
    const float* b1  = (const float*)d_in[3];
    const float* W1r = (const float*)d_in[4];
    const float* W2l = (const float*)d_in[5];
    const float* b2  = (const float*)d_in[6];
    const float* W2r = (const float*)d_in[7];
    const float* Wm1 = (const float*)d_in[8];
    const float* bm1 = (const float*)d_in[9];
    const float* Wm2 = (const float*)d_in[10];
    const float* bm2 = (const float*)d_in[11];
    float* out = (float*)d_out;

    int n = in_sizes[0] / HDIM;
    int e = in_sizes[1] / 2;
    int ntiles = (n + 127) / 128;

    const int SMEM_GEMM = 2 * 128 * SROW * 4;   // 135168 B
    cudaFuncSetAttribute(k_mmagemm<0>, cudaFuncAttributeMaxDynamicSharedMemorySize, SMEM_GEMM);
    cudaFuncSetAttribute(k_mmagemm<1>, cudaFuncAttributeMaxDynamicSharedMemorySize, SMEM_GEMM);
    cudaFuncSetAttribute(k_mmagemm<2>, cudaFuncAttributeMaxDynamicSharedMemorySize, SMEM_GEMM);

    // dtype detection + CSR build
    k_detect<<<1, 256>>>((const unsigned*)ei, e);
    k_zero_hist<<<(n + 255) / 256, 256>>>(n);
    k_hist<<<(e + 255) / 256, 256>>>(ei, e, n);
    int nb = (n + 2047) / 2048;
    k_scan1<<<nb, 512>>>(n);
    k_scan2<<<1, 128>>>(nb, n);
    k_scan3<<<nb, 512>>>(n);
    k_scatter<<<(e + 255) / 256, 256>>>(ei, e, n);

    int aggBlocks = (n + 7) / 8;

    // layer 1
    k_aggregate<true><<<aggBlocks, 256>>>((const float4*)x, n);
    k_mmagemm<0><<<ntiles, 256, SMEM_GEMM>>>((const float4*)x, (const float4*)W1l,
                                             (const float4*)W1r, b1, n);
    // layer 2
    k_aggregate<false><<<aggBlocks, 256>>>(nullptr, n);
    k_mmagemm<1><<<ntiles, 256, SMEM_GEMM>>>(nullptr, (const float4*)W2l,
                                             (const float4*)W2r, b2, n);
    // MLP layer
    k_mmagemm<2><<<ntiles, 256, SMEM_GEMM>>>(nullptr, (const float4*)Wm1, nullptr, bm1, n);
    // head
    int headBlocks = (n + 31) / 32;
    k_head<<<headBlocks, 256>>>(Wm2, bm2, out, n);
}